// round 17
// baseline (speedup 1.0000x reference)
#include <cuda_runtime.h>
#include <cstdint>

// B=8, M=512, A=16, F=128. Dense register-resident contraction:
//   out[d,f] = sum_c y[c,f] * ( sum_a cgc[a,d,c] * x[a,f] )
// d-PACKED coefficients: one LDS.128 = 4 coefficients ({d0,d1} x 2 a's).
// x duplicated {x,x} into persistent regs. Work unit = (tile, dp-pass):
// 8192 units over 1184 static warp slots (~1% tail). Coefficient double-
// buffer pipelined ACROSS c iterations (no cold-start bubble per c).
// Static striding, no atomics, single kernel. 296 blocks (2/SM).

#define AA 16
#define TILE_FLOATS 2048
#define THREADS 128
#define GRID_BLOCKS 296
#define WSLOTS (GRID_BLOCKS * 4)

typedef unsigned long long ull;

__device__ __forceinline__ ull fma2(ull a, ull b, ull c) {
    ull d;
    asm("fma.rn.f32x2 %0, %1, %2, %3;" : "=l"(d) : "l"(a), "l"(b), "l"(c));
    return d;
}
__device__ __forceinline__ ull dup32(float v) {
    unsigned int u = __float_as_uint(v);
    return ((ull)u << 32) | u;
}
__device__ __forceinline__ float ulo(ull v) { return __uint_as_float((unsigned int)v); }
__device__ __forceinline__ float uhi(ull v) { return __uint_as_float((unsigned int)(v >> 32)); }

// load a 4-entry coefficient group (4 x LDS.128) from pointer p at entry base
#define LOADQ(buf, p, base)           \
    {                                 \
        buf[0] = (p)[(base) + 0];     \
        buf[1] = (p)[(base) + 1];     \
        buf[2] = (p)[(base) + 2];     \
        buf[3] = (p)[(base) + 3];     \
    }

// 32 FFMA2 consuming one 4-entry group; ab = a-base (0 or 8)
#define FMAG(buf, ab)                                       \
    {                                                       \
        _Pragma("unroll")                                   \
        for (int q = 0; q < 4; ++q) {                       \
            const ulonglong2 gg = buf[q];                   \
            const int a0 = ((ab) + q * 2) * 4;              \
            const int a1 = ((ab) + q * 2 + 1) * 4;          \
            t0 = fma2(gg.x, xd[a0 + 0], t0);                \
            t1 = fma2(gg.x, xd[a0 + 1], t1);                \
            t2 = fma2(gg.x, xd[a0 + 2], t2);                \
            t3 = fma2(gg.x, xd[a0 + 3], t3);                \
            t0 = fma2(gg.y, xd[a1 + 0], t0);                \
            t1 = fma2(gg.y, xd[a1 + 1], t1);                \
            t2 = fma2(gg.y, xd[a1 + 2], t2);                \
            t3 = fma2(gg.y, xd[a1 + 3], t3);                \
        }                                                   \
    }

// fold t into acc for local d-pair dpl, then reset t
#define ACCUM(dpl)                                              \
    {                                                           \
        acc[(dpl) * 4 + 0] = fma2(t0, yd0, acc[(dpl) * 4 + 0]); \
        acc[(dpl) * 4 + 1] = fma2(t1, yd1, acc[(dpl) * 4 + 1]); \
        acc[(dpl) * 4 + 2] = fma2(t2, yd2, acc[(dpl) * 4 + 2]); \
        acc[(dpl) * 4 + 3] = fma2(t3, yd3, acc[(dpl) * 4 + 3]); \
        t0 = t1 = t2 = t3 = 0ull;                               \
    }

__global__ __launch_bounds__(THREADS, 2) void tp_dense_kernel(
    const float* __restrict__ x,
    const float* __restrict__ y,
    const float* __restrict__ cgc,
    float* __restrict__ out,
    int n_bm)
{
    // Staged cgc, d-pair packed: gdpk[c][dp][a] = {g[a,2dp,c], g[a,2dp+1,c]}
    __shared__ float sc[AA * AA * AA];          // 16 KB linear copy
    __shared__ __align__(16) ull gdpk[2048];    // 16 KB packed

    const int tid = threadIdx.x;

#pragma unroll
    for (int j = tid; j < AA * AA * AA; j += THREADS) sc[j] = cgc[j];
    __syncthreads();
#pragma unroll
    for (int s = tid; s < 2048; s += THREADS) {
        const int c  = s >> 7;
        const int dp = (s >> 4) & 7;
        const int a  = s & 15;
        const unsigned int lo = __float_as_uint(sc[a * 256 + dp * 32 + c]);
        const unsigned int hi = __float_as_uint(sc[a * 256 + dp * 32 + 16 + c]);
        gdpk[s] = ((ull)hi << 32) | lo;
    }
    __syncthreads();

    const int wid   = tid >> 5;
    const int lane  = tid & 31;
    const int wslot = blockIdx.x * 4 + wid;
    const int n_units = n_bm * 2;

    // Static stride over fine-grained units: unit = (tile, dp-pass)
    for (int u = wslot; u < n_units; u += WSLOTS) {
        const int bm    = u >> 1;
        const int dbase = (u & 1) * 4;   // dp base for this pass

        const float4* xg4 = (const float4*)(x + (size_t)bm * TILE_FLOATS);
        const float4* yg4 = (const float4*)(y + (size_t)bm * TILE_FLOATS);
        float4*       og4 = (float4*)(out + (size_t)bm * TILE_FLOATS);

        // x tile -> duplicated regs
        ull xd[AA * 4];
#pragma unroll
        for (int a = 0; a < AA; ++a) {
            const float4 xv = xg4[a * 32 + lane];
            xd[a * 4 + 0] = dup32(xv.x);
            xd[a * 4 + 1] = dup32(xv.y);
            xd[a * 4 + 2] = dup32(xv.z);
            xd[a * 4 + 3] = dup32(xv.w);
        }

        ull acc[16];
#pragma unroll
        for (int i = 0; i < 16; ++i) acc[i] = 0ull;

        float4 yv = yg4[lane];

        // Pipeline prologue: group0 of c=0 pre-loaded into bufA
        const ulonglong2* gc = (const ulonglong2*)(gdpk + dbase * 16);
        ulonglong2 bufA[4], bufB[4];
        ull t0 = 0ull, t1 = 0ull, t2 = 0ull, t3 = 0ull;
        LOADQ(bufA, gc, 0);

#pragma unroll 1
        for (int c = 0; c < AA; ++c) {
            const ull yd0 = dup32(yv.x);
            const ull yd1 = dup32(yv.y);
            const ull yd2 = dup32(yv.z);
            const ull yd3 = dup32(yv.w);
            yv = yg4[((c + 1) & 15) * 32 + lane];   // prefetch next c's y

            const ulonglong2* gcn =
                (const ulonglong2*)(gdpk + ((c + 1) & 15) * 128 + dbase * 16);

            // 8 groups; last load fetches group0 of NEXT c (no cold start)
            LOADQ(bufB, gc, 4);    FMAG(bufA, 0);
            LOADQ(bufA, gc, 8);    FMAG(bufB, 8);  ACCUM(0);
            LOADQ(bufB, gc, 12);   FMAG(bufA, 0);
            LOADQ(bufA, gc, 16);   FMAG(bufB, 8);  ACCUM(1);
            LOADQ(bufB, gc, 20);   FMAG(bufA, 0);
            LOADQ(bufA, gc, 24);   FMAG(bufB, 8);  ACCUM(2);
            LOADQ(bufB, gc, 28);   FMAG(bufA, 0);
            LOADQ(bufA, gcn, 0);   FMAG(bufB, 8);  ACCUM(3);

            gc = gcn;
        }

        // Epilogue: unpack d-pairs -> two float4 rows per dp
#pragma unroll
        for (int dpl = 0; dpl < 4; ++dpl) {
            const int dp = (dbase >> 0) + dpl;   // dp in [dbase, dbase+4)
            const float4 o0 = make_float4(
                ulo(acc[dpl * 4 + 0]), ulo(acc[dpl * 4 + 1]),
                ulo(acc[dpl * 4 + 2]), ulo(acc[dpl * 4 + 3]));
            const float4 o1 = make_float4(
                uhi(acc[dpl * 4 + 0]), uhi(acc[dpl * 4 + 1]),
                uhi(acc[dpl * 4 + 2]), uhi(acc[dpl * 4 + 3]));
            og4[(dp * 2) * 32 + lane]     = o0;
            og4[(dp * 2 + 1) * 32 + lane] = o1;
        }
    }
}

extern "C" void kernel_launch(void* const* d_in, const int* in_sizes, int n_in,
                              void* d_out, int out_size) {
    const float* x   = (const float*)d_in[0];
    const float* y   = (const float*)d_in[1];
    const float* cgc = (const float*)d_in[2];
    float* out = (float*)d_out;

    const int n_bm = in_sizes[0] / TILE_FLOATS;   // 4096

    tp_dense_kernel<<<GRID_BLOCKS, THREADS>>>(x, y, cgc, out, n_bm);
}